// round 14
// baseline (speedup 1.0000x reference)
#include <cuda_runtime.h>

#define NB 32
#define NC 256
#define NH 64
#define NW 64
#define NM 16
#define EPSV 1e-5f
#define RPB 103   // blocks per batch: 32 reduce + 7 mid + 64 final

// Scratch (allocation-free rule: __device__ globals)
__device__ __align__(16) float g_xh[NB*NC*NH];        // mean over w: (b,c,h)
__device__ __align__(16) float g_xw[NB*NC*NW];        // mean over h: (b,c,w)
__device__ __align__(16) float g_pooled[NB*NC];       // mean over (h,w)
__device__ __align__(16) float g_part[NB*32*NH*NW];   // per-chunk channel partials
__device__ __align__(16) float g_fch[NB*NC];
__device__ __align__(16) float g_fsa[NB*NH*NW];
__device__ __align__(16) float g_sh[NB*NC*NH];
__device__ __align__(16) float g_sw[NB*NC*NW];
// Pipeline flags (zero-initialized; k_clear re-zeroes after each run)
__device__ int g_red_done[NB];
__device__ int g_mid_done[NB];

__global__ __launch_bounds__(256, 4) void k_pipe(
    const float* __restrict__ x,
    const float* __restrict__ w10, const float* __restrict__ w11,
    const float* __restrict__ gamma, const float* __restrict__ beta,
    const float* __restrict__ mean, const float* __restrict__ var,
    const float* __restrict__ w20, const float* __restrict__ w21,
    float* __restrict__ out) {
    __shared__ __align__(16) char smem_u[49152];
    int bid = blockIdx.x;
    int b = bid / RPB;
    int r = bid - b * RPB;
    int t = threadIdx.x;

    if (r < 32) {
        // ───── REDUCE role: chunk r of 8 channels (R13-proven inner loop) ─────
        int chunk = r;
        int lane = t & 31, warp = t >> 5;
        float (*s_row)[1024] = (float(*)[1024])smem_u;            // 32KB
        float4 (*s_col)[8][16] = (float4(*)[8][16])(smem_u + 32768); // 16KB
        float4 ch[4];
#pragma unroll
        for (int i = 0; i < 4; i++) ch[i] = make_float4(0.f, 0.f, 0.f, 0.f);

        const float4* base = (const float4*)x + ((size_t)b * NC + chunk * 8) * 1024 + t;
        float* gxh = g_xh + ((size_t)b * NC + chunk * 8) * NH;
        float4 buf[2][4];
#pragma unroll
        for (int i = 0; i < 4; i++) buf[0][i] = __ldcg(base + i * 256);

#pragma unroll
        for (int ci = 0; ci < 8; ci++) {
            int cur = ci & 1;
            if (ci < 7) {
#pragma unroll
                for (int i = 0; i < 4; i++)
                    buf[cur ^ 1][i] = __ldcg(base + (ci + 1) * 1024 + i * 256);
            }
            float4 ca = make_float4(0.f, 0.f, 0.f, 0.f);
#pragma unroll
            for (int i = 0; i < 4; i++) {
                float4 v = buf[cur][i];
                ch[i].x += v.x; ch[i].y += v.y; ch[i].z += v.z; ch[i].w += v.w;
                ca.x += v.x; ca.y += v.y; ca.z += v.z; ca.w += v.w;
                float rs = (v.x + v.y) + (v.z + v.w);
                int q = i * 256 + t;
                s_row[ci][(q & 0x3F0) | ((q ^ (q >> 4)) & 15)] = rs;
            }
            ca.x += __shfl_xor_sync(0xffffffffu, ca.x, 16);
            ca.y += __shfl_xor_sync(0xffffffffu, ca.y, 16);
            ca.z += __shfl_xor_sync(0xffffffffu, ca.z, 16);
            ca.w += __shfl_xor_sync(0xffffffffu, ca.w, 16);
            if (lane < 16) s_col[ci][warp][lane] = ca;
        }
        __syncthreads();

        // Tail A: row sums
#pragma unroll
        for (int r2 = 0; r2 < 2; r2++) {
            int p = r2 * 256 + t;
            int ci = p >> 6, row = p & 63;
            const float* sr = s_row[ci] + row * 16;
            float s = 0.f;
#pragma unroll
            for (int k = 0; k < 16; k++) s += sr[(k ^ row) & 15];
            gxh[ci * NH + row] = s * (1.f / NW);
        }
        // Tail B: column sums + pooled
        if (t < 128) {
            int ci = t >> 4, wq = t & 15;
            float4 s = s_col[ci][0][wq];
#pragma unroll
            for (int wv = 1; wv < 8; wv++) {
                float4 p = s_col[ci][wv][wq];
                s.x += p.x; s.y += p.y; s.z += p.z; s.w += p.w;
            }
            int c = chunk * 8 + ci;
            ((float4*)g_xw)[((size_t)b * NC + c) * 16 + wq] =
                make_float4(s.x * (1.f / NH), s.y * (1.f / NH),
                            s.z * (1.f / NH), s.w * (1.f / NH));
            float tot = s.x + s.y + s.z + s.w;
            tot += __shfl_xor_sync(0xffffffffu, tot, 8);
            tot += __shfl_xor_sync(0xffffffffu, tot, 4);
            tot += __shfl_xor_sync(0xffffffffu, tot, 2);
            tot += __shfl_xor_sync(0xffffffffu, tot, 1);
            if (wq == 0) g_pooled[b * NC + c] = tot * (1.f / (NH * NW));
        }
        // channel-partial store
        float4* pp = (float4*)g_part + ((size_t)b * 32 + chunk) * 1024 + t;
#pragma unroll
        for (int i = 0; i < 4; i++) pp[i * 256] = ch[i];

        // release
        __threadfence();
        __syncthreads();
        if (t == 0) atomicAdd(&g_red_done[b], 1);

    } else if (r < 39) {
        // ───── MID role: wait for all 32 reduce blocks of this b ─────
        if (t == 0) {
            while (*(volatile int*)&g_red_done[b] < 32) __nanosleep(128);
            __threadfence();
        }
        __syncthreads();
        int mr = r - 32;

        if (mr < 2) {
            // attn MLP, half = mr (0: h positions, 1: w positions), 256 threads
            float* s_w10t = (float*)smem_u;            // [c][m] 16KB
            float* s_w11  = (float*)(smem_u + 16384);  // [c][m] 16KB
            float* s_y    = (float*)(smem_u + 32768);  // [m][64] 4KB
            float* s_inv  = (float*)(smem_u + 36864);
            float* s_bias = (float*)(smem_u + 36928);
            int half = mr;
            int lsub = t & 63, grp = t >> 6;
#pragma unroll
            for (int k = 0; k < 16; k++) {
                int idx = k * 256 + t;
                int m = idx >> 8, c = idx & 255;
                s_w10t[c * NM + m] = w10[idx];
                s_w11[idx] = w11[idx];
            }
            if (t < NM) {
                float inv = rsqrtf(var[t] + EPSV) * gamma[t];
                s_inv[t] = inv;
                s_bias[t] = beta[t] - mean[t] * inv;
            }
            __syncthreads();

            const float* catp = (half == 0 ? g_xh : g_xw) + (size_t)b * NC * 64 + lsub;
            float a0 = 0.f, a1 = 0.f, a2 = 0.f, a3 = 0.f;
#pragma unroll 16
            for (int c = 0; c < NC; c++) {
                float cv = __ldg(catp + (size_t)c * 64);
                float4 wv = *(const float4*)&s_w10t[c * NM + grp * 4];
                a0 = fmaf(wv.x, cv, a0);
                a1 = fmaf(wv.y, cv, a1);
                a2 = fmaf(wv.z, cv, a2);
                a3 = fmaf(wv.w, cv, a3);
            }
            int m0 = grp * 4;
            s_y[(m0 + 0) * 64 + lsub] = fmaxf(fmaf(a0, s_inv[m0 + 0], s_bias[m0 + 0]), 0.f);
            s_y[(m0 + 1) * 64 + lsub] = fmaxf(fmaf(a1, s_inv[m0 + 1], s_bias[m0 + 1]), 0.f);
            s_y[(m0 + 2) * 64 + lsub] = fmaxf(fmaf(a2, s_inv[m0 + 2], s_bias[m0 + 2]), 0.f);
            s_y[(m0 + 3) * 64 + lsub] = fmaxf(fmaf(a3, s_inv[m0 + 3], s_bias[m0 + 3]), 0.f);
            __syncthreads();

            float yr[NM];
#pragma unroll
            for (int m = 0; m < NM; m++) yr[m] = s_y[m * 64 + lsub];
            float* dst = (half == 0 ? g_sh : g_sw) + (size_t)b * NC * 64 + lsub;
#pragma unroll 4
            for (int it = 0; it < 64; it++) {
                int c = it * 4 + grp;
                const float4* wr = (const float4*)&s_w11[c * NM];
                float4 q0 = wr[0], q1 = wr[1], q2 = wr[2], q3 = wr[3];
                float ae = 0.f, ao = 0.f;
                ae = fmaf(q0.x, yr[0], ae);  ao = fmaf(q0.y, yr[1], ao);
                ae = fmaf(q0.z, yr[2], ae);  ao = fmaf(q0.w, yr[3], ao);
                ae = fmaf(q1.x, yr[4], ae);  ao = fmaf(q1.y, yr[5], ao);
                ae = fmaf(q1.z, yr[6], ae);  ao = fmaf(q1.w, yr[7], ao);
                ae = fmaf(q2.x, yr[8], ae);  ao = fmaf(q2.y, yr[9], ao);
                ae = fmaf(q2.z, yr[10], ae); ao = fmaf(q2.w, yr[11], ao);
                ae = fmaf(q3.x, yr[12], ae); ao = fmaf(q3.y, yr[13], ao);
                ae = fmaf(q3.z, yr[14], ae); ao = fmaf(q3.w, yr[15], ao);
                dst[(size_t)c * 64] = 1.f / (1.f + __expf(-(ae + ao)));
            }
        } else if (mr < 6) {
            // f_sa: 16 output rows per block (tile = mr-2), 256 threads
            float (*s_m)[64] = (float(*)[64])smem_u;   // [18][64] w/ halo
            int tile = mr - 2;
            int h0 = tile * 16;
            const float4* pb = (const float4*)g_part + (size_t)b * 32 * 1024;
#pragma unroll
            for (int pass = 0; pass < 2; pass++) {
                int qi = pass * 256 + t;
                if (qi < 288) {
                    int lr = qi >> 4, wq = qi & 15;
                    int hh = h0 - 1 + lr;
                    float4 acc = make_float4(0.f, 0.f, 0.f, 0.f);
                    if (hh >= 0 && hh < NH) {
                        int poff = hh * 16 + wq;
#pragma unroll 8
                        for (int ck = 0; ck < 32; ck++) {
                            float4 v = __ldg(pb + ck * 1024 + poff);
                            acc.x += v.x; acc.y += v.y; acc.z += v.z; acc.w += v.w;
                        }
                    }
                    *(float4*)&s_m[lr][wq * 4] =
                        make_float4(acc.x * (1.f / NC), acc.y * (1.f / NC),
                                    acc.z * (1.f / NC), acc.w * (1.f / NC));
                }
            }
            float kk[9];
#pragma unroll
            for (int i = 0; i < 9; i++) kk[i] = w21[i];
            __syncthreads();
            int row = t >> 4, lr = row + 1;
            int w0 = (t & 15) * 4;
            float4 o;
            float* op = (float*)&o;
#pragma unroll
            for (int j = 0; j < 4; j++) {
                int w = w0 + j;
                float acc = 0.f;
#pragma unroll
                for (int dh = -1; dh <= 1; dh++) {
#pragma unroll
                    for (int dw = -1; dw <= 1; dw++) {
                        int ww = w + dw;
                        if (ww >= 0 && ww < NW)
                            acc += s_m[lr + dh][ww] * kk[(dh + 1) * 3 + (dw + 1)];
                    }
                }
                op[j] = 1.f / (1.f + __expf(-acc));
            }
            ((float4*)g_fsa)[(size_t)b * 1024 + (h0 + row) * 16 + (t & 15)] = o;
        } else {
            // f_ch: 5-tap SAME conv over pooled channels (c = t)
            float acc = 0.f;
#pragma unroll
            for (int k = 0; k < 5; k++) {
                int c2 = t + k - 2;
                if (c2 >= 0 && c2 < NC)
                    acc += __ldg(&g_pooled[b * NC + c2]) * w20[k];
            }
            g_fch[b * NC + t] = acc;
        }

        __threadfence();
        __syncthreads();
        if (t == 0) atomicAdd(&g_mid_done[b], 1);

    } else {
        // ───── FINAL role: wait for all 7 mid blocks of this b ─────
        if (t == 0) {
            while (*(volatile int*)&g_mid_done[b] < 7) __nanosleep(128);
            __threadfence();
        }
        __syncthreads();
        int cg = r - 39;                    // 0..63, 4 channels each
        int bc0 = b * NC + cg * 4;
        float (*s_sh)[64] = (float(*)[64])smem_u;          // 1KB
        float (*s_sw)[64] = (float(*)[64])(smem_u + 1024); // 1KB
#pragma unroll
        for (int j = 0; j < 2; j++) {
            int p = j * 256 + t;
            int cc = p >> 6, hh = p & 63;
            if (cc < 4) s_sh[cc][hh] = g_sh[(size_t)(bc0 + cc) * 64 + hh];
            else        s_sw[cc - 4][hh] = g_sw[(size_t)(bc0 + cc - 4) * 64 + hh];
        }
        float fch[4];
#pragma unroll
        for (int c = 0; c < 4; c++) fch[c] = g_fch[bc0 + c];
        __syncthreads();
        const float4* xp = (const float4*)x + (size_t)bc0 * 1024;
        float4* op = (float4*)out + (size_t)bc0 * 1024;
        const float4* fp = (const float4*)g_fsa + (size_t)b * 1024;
#pragma unroll
        for (int i = 0; i < 4; i++) {
            int q = i * 256 + t;
            float4 fv = __ldg(fp + q);
            int rr = q >> 4;
            float4 xv[4];
#pragma unroll
            for (int c = 0; c < 4; c++) xv[c] = __ldcg(xp + c * 1024 + q);
#pragma unroll
            for (int c = 0; c < 4; c++) {
                float sh = s_sh[c][rr];
                float4 swv = ((const float4*)s_sw[c])[q & 15];
                float4 o;
                o.x = xv[c].x * (fch[c] + sh * swv.x + fv.x);
                o.y = xv[c].y * (fch[c] + sh * swv.y + fv.y);
                o.z = xv[c].z * (fch[c] + sh * swv.z + fv.z);
                o.w = xv[c].w * (fch[c] + sh * swv.w + fv.w);
                __stcs(op + c * 1024 + q, o);
            }
        }
    }
}

// Reset pipeline flags for the next graph replay.
__global__ void k_clear() {
    int t = threadIdx.x;
    if (t < NB) { g_red_done[t] = 0; g_mid_done[t] = 0; }
}

extern "C" void kernel_launch(void* const* d_in, const int* in_sizes, int n_in,
                              void* d_out, int out_size) {
    const float* x     = (const float*)d_in[0];
    const float* w10   = (const float*)d_in[1];
    const float* w11   = (const float*)d_in[2];
    const float* gamma = (const float*)d_in[3];
    const float* beta  = (const float*)d_in[4];
    const float* mean  = (const float*)d_in[5];
    const float* var   = (const float*)d_in[6];
    const float* w20   = (const float*)d_in[7];
    const float* w21   = (const float*)d_in[8];
    float* out = (float*)d_out;

    k_pipe<<<NB * RPB, 256>>>(x, w10, w11, gamma, beta, mean, var, w20, w21, out);
    k_clear<<<1, 32>>>();
}